// round 4
// baseline (speedup 1.0000x reference)
#include <cuda_runtime.h>
#include <cstdint>

// Problem constants (fixed shapes)
#define B   4
#define NB  2048
#define BS  32
#define D   256
#define NF  512
#define NC  1024
#define D4  (D/4)              // 64 float4 per row
#define TILE_F4 (BS * D4)      // 2048 float4 per (b,f) tile = 32 KB

#define TILES_PER_CTA 4
#define FINE_CTAS     ((B * NF) / TILES_PER_CTA)   // 512
#define COARSE_BLOCKS ((B * NC * D4) / 256)        // 1024
#define SCALAR_BLOCKS ((B * NF * BS) / 256)        // 256
// Grid order: scalar | coarse | fine  (small work first, heavy tail = fine+TMA)
#define TOTAL_BLOCKS  (SCALAR_BLOCKS + COARSE_BLOCKS + FINE_CTAS)

#define SMEM_BYTES (2 * TILE_F4 * sizeof(float4))  // 64 KB double buffer

__global__ void __launch_bounds__(256) fused_kernel(
    const float4* __restrict__ coarse,    // [B,NB,D4]
    const float4* __restrict__ bank,      // [B,NB,BS,D4]
    const int*    __restrict__ fidx,      // [B,NF]
    const int*    __restrict__ table,     // [B,NB]
    const float*  __restrict__ ftm,       // [B, NB*BS]
    const float*  __restrict__ fscore,    // [B, NF]
    const float*  __restrict__ ctm,       // [B, NB]
    const int*    __restrict__ cidx,      // [B, NC]
    const float*  __restrict__ cscore,    // [B, NC]
    float4* __restrict__ o_fine_states,   // [B*NF] tiles of 2048 f4
    float*  __restrict__ o_fine_mask,
    float*  __restrict__ o_fine_scores,
    float*  __restrict__ o_fine_dups,
    float4* __restrict__ o_coarse_states, // [B,NC,D4]
    float*  __restrict__ o_coarse_mask,
    float*  __restrict__ o_coarse_scores,
    float*  __restrict__ o_coarse_dups)
{
    extern __shared__ __align__(128) float4 obuf[];   // [2][TILE_F4]

    const unsigned bid = blockIdx.x;
    const unsigned t   = threadIdx.x;

    if (bid < SCALAR_BLOCKS) {
        // ---- all scalar outputs ----
        const unsigned i = bid * 256 + t;             // < 65536
        const unsigned s = i & (BS - 1);
        const unsigned f = (i >> 5) & (NF - 1);
        const unsigned b = i >> 14;

        const int fi = __ldg(&fidx[b * NF + f]);
        o_fine_mask[i]   = __ldg(&ftm[b * (NB * BS) + (unsigned)fi * BS + s]);
        o_fine_scores[i] = __ldg(&fscore[b * NF + f]);
        o_fine_dups[i]   = 1.0f;

        if (i < (unsigned)(B * NC)) {
            const unsigned c  = i & (NC - 1);
            const unsigned b2 = i >> 10;
            const int ci = __ldg(&cidx[b2 * NC + c]);
            o_coarse_mask[i]   = __ldg(&ctm[b2 * NB + (unsigned)ci]);
            o_coarse_scores[i] = __ldg(&cscore[i]);
            o_coarse_dups[i]   = 32.0f;
        }
    }
    else if (bid < SCALAR_BLOCKS + COARSE_BLOCKS) {
        // ---- coarse token states gather ----
        const unsigned i  = (bid - SCALAR_BLOCKS) * 256 + t;  // < B*NC*D4 = 2^18
        const unsigned d4 = i & (D4 - 1);
        const unsigned c  = (i >> 6) & (NC - 1);
        const unsigned b  = i >> 16;

        const int ci = __ldg(&cidx[b * NC + c]);
        o_coarse_states[i] = __ldg(&coarse[(b * NB + (unsigned)ci) * D4 + d4]);
    }
    else {
        // ---- fine token states: 4 tiles per CTA, double-buffered TMA store ----
        const unsigned g = bid - (SCALAR_BLOCKS + COARSE_BLOCKS);   // < 512

        #pragma unroll
        for (int k = 0; k < TILES_PER_CTA; k++) {
            const unsigned tile = g * TILES_PER_CTA + (unsigned)k;  // < 2048
            const unsigned b = tile >> 9;        // / NF
            const unsigned f = tile & (NF - 1);

            const int fi = __ldg(&fidx[b * NF + f]);
            // d4 for every element this thread touches is (t & 63): 256 % 64 == 0
            const float4 c = __ldg(&coarse[(b * NB + (unsigned)fi) * D4 + (t & (D4 - 1))]);
            const int bi = __ldg(&table[b * NB + fi]);

            const float4* __restrict__ bt = bank + (size_t)(b * NB + (unsigned)bi) * TILE_F4;

            float4 v[8];
            #pragma unroll
            for (int j = 0; j < 8; j++)
                v[j] = __ldg(&bt[j * 256 + t]);

            // Ensure the bulk store that last read this buffer (iter k-2) is done.
            if (t == 0)
                asm volatile("cp.async.bulk.wait_group.read 1;" ::: "memory");
            __syncthreads();

            float4* buf = obuf + (unsigned)(k & 1) * TILE_F4;
            #pragma unroll
            for (int j = 0; j < 8; j++) {
                buf[j * 256 + t] = make_float4(c.x - v[j].x, c.y - v[j].y,
                                               c.z - v[j].z, c.w - v[j].w);
            }
            // Make generic-proxy smem writes visible to the async (TMA) proxy.
            asm volatile("fence.proxy.async.shared::cta;" ::: "memory");
            __syncthreads();

            if (t == 0) {
                const uint32_t saddr =
                    (uint32_t)__cvta_generic_to_shared(buf);
                float4* gdst = o_fine_states + (size_t)tile * TILE_F4;
                asm volatile(
                    "cp.async.bulk.global.shared::cta.bulk_group [%0], [%1], %2;"
                    :: "l"(gdst), "r"(saddr), "r"((uint32_t)(TILE_F4 * 16))
                    : "memory");
                asm volatile("cp.async.bulk.commit_group;" ::: "memory");
            }
        }

        // Drain pending bulk stores before smem is deallocated at CTA exit.
        if (t == 0)
            asm volatile("cp.async.bulk.wait_group.read 0;" ::: "memory");
        __syncthreads();
    }
}

extern "C" void kernel_launch(void* const* d_in, const int* in_sizes, int n_in,
                              void* d_out, int out_size)
{
    const float* fine_token_mask      = (const float*)d_in[0];
    const float* coarse_token_states  = (const float*)d_in[1];
    const float* coarse_token_mask    = (const float*)d_in[2];
    const int*   fine_block_indices   = (const int*)  d_in[3];
    const float* fine_block_scores    = (const float*)d_in[4];
    const int*   coarse_block_indices = (const int*)  d_in[5];
    const float* coarse_block_scores  = (const float*)d_in[6];
    const int*   cache_indice_table   = (const int*)  d_in[7];
    const float* cache_bank           = (const float*)d_in[8];

    float* out = (float*)d_out;

    const long long n_fine_states   = (long long)B * NF * BS * D;   // 16,777,216
    const long long n_fine_scalar   = (long long)B * NF * BS;       // 65,536
    const long long n_coarse_states = (long long)B * NC * D;        // 1,048,576
    const long long n_coarse_scalar = (long long)B * NC;            // 4,096

    float* o_fine_states   = out;
    float* o_fine_mask     = o_fine_states   + n_fine_states;
    float* o_fine_scores   = o_fine_mask     + n_fine_scalar;
    float* o_fine_dups     = o_fine_scores   + n_fine_scalar;
    float* o_coarse_states = o_fine_dups     + n_fine_scalar;
    float* o_coarse_mask   = o_coarse_states + n_coarse_states;
    float* o_coarse_scores = o_coarse_mask   + n_coarse_scalar;
    float* o_coarse_dups   = o_coarse_scores + n_coarse_scalar;

    cudaFuncSetAttribute(fused_kernel,
                         cudaFuncAttributeMaxDynamicSharedMemorySize,
                         (int)SMEM_BYTES);

    fused_kernel<<<TOTAL_BLOCKS, 256, SMEM_BYTES>>>(
        (const float4*)coarse_token_states,
        (const float4*)cache_bank,
        fine_block_indices,
        cache_indice_table,
        fine_token_mask,
        fine_block_scores,
        coarse_token_mask,
        coarse_block_indices,
        coarse_block_scores,
        (float4*)o_fine_states,
        o_fine_mask, o_fine_scores, o_fine_dups,
        (float4*)o_coarse_states,
        o_coarse_mask, o_coarse_scores, o_coarse_dups);
}

// round 5
// speedup vs baseline: 1.2500x; 1.2500x over previous
#include <cuda_runtime.h>
#include <cstdint>

// Problem constants (fixed shapes)
#define B   4
#define NB  2048
#define BS  32
#define D   256
#define NF  512
#define NC  1024
#define D4  (D/4)              // 64 float4 per row
#define TILE_F4 (BS * D4)      // 2048 float4 per (b,f) tile

// Grid partition: scalar | coarse | fine
#define SCALAR_BLOCKS  64      // 65536 scalars, 1024 per block (4 per thread)
#define COARSE_BLOCKS  256     // 2^18 float4, 1024 per block (4 per thread)
#define FINE_CTAS      1024    // 2048 tiles, 2 per CTA
#define TOTAL_BLOCKS   (SCALAR_BLOCKS + COARSE_BLOCKS + FINE_CTAS)   // 1344

__global__ void __launch_bounds__(256) fused_kernel(
    const float4* __restrict__ coarse,    // [B,NB,D4]
    const float4* __restrict__ bank,      // [B,NB,BS,D4]
    const int*    __restrict__ fidx,      // [B,NF]
    const int*    __restrict__ table,     // [B,NB]
    const float*  __restrict__ ftm,       // [B, NB*BS]
    const float*  __restrict__ fscore,    // [B, NF]
    const float*  __restrict__ ctm,       // [B, NB]
    const int*    __restrict__ cidx,      // [B, NC]
    const float*  __restrict__ cscore,    // [B, NC]
    float4* __restrict__ o_fine_states,   // [B*NF] tiles of 2048 f4
    float*  __restrict__ o_fine_mask,
    float*  __restrict__ o_fine_scores,
    float*  __restrict__ o_fine_dups,
    float4* __restrict__ o_coarse_states, // [B,NC,D4]
    float*  __restrict__ o_coarse_mask,
    float*  __restrict__ o_coarse_scores,
    float*  __restrict__ o_coarse_dups)
{
    const unsigned bid = blockIdx.x;
    const unsigned t   = threadIdx.x;

    if (bid < SCALAR_BLOCKS) {
        // ---- all scalar outputs: 4 elements per thread ----
        #pragma unroll
        for (int j = 0; j < 4; j++) {
            const unsigned i = bid * 1024 + (unsigned)j * 256 + t;  // < 65536
            const unsigned s = i & (BS - 1);
            const unsigned f = (i >> 5) & (NF - 1);
            const unsigned b = i >> 14;

            const int fi = __ldg(&fidx[b * NF + f]);
            o_fine_mask[i]   = __ldg(&ftm[b * (NB * BS) + (unsigned)fi * BS + s]);
            o_fine_scores[i] = __ldg(&fscore[b * NF + f]);
            o_fine_dups[i]   = 1.0f;

            if (i < (unsigned)(B * NC)) {
                const unsigned c  = i & (NC - 1);
                const unsigned b2 = i >> 10;
                const int ci = __ldg(&cidx[b2 * NC + c]);
                o_coarse_mask[i]   = __ldg(&ctm[b2 * NB + (unsigned)ci]);
                o_coarse_scores[i] = __ldg(&cscore[i]);
                o_coarse_dups[i]   = 32.0f;
            }
        }
    }
    else if (bid < SCALAR_BLOCKS + COARSE_BLOCKS) {
        // ---- coarse token states gather: 4 float4 per thread (MLP=4) ----
        const unsigned base = (bid - SCALAR_BLOCKS) * 1024;
        float4 v[4];
        #pragma unroll
        for (int j = 0; j < 4; j++) {
            const unsigned i  = base + (unsigned)j * 256 + t;  // < 2^18
            const unsigned d4 = i & (D4 - 1);
            const unsigned c  = (i >> 6) & (NC - 1);
            const unsigned b  = i >> 16;
            const int ci = __ldg(&cidx[b * NC + c]);
            v[j] = __ldg(&coarse[(b * NB + (unsigned)ci) * D4 + d4]);
        }
        #pragma unroll
        for (int j = 0; j < 4; j++)
            __stwt(&o_coarse_states[base + (unsigned)j * 256 + t], v[j]);
    }
    else {
        // ---- fine token states: 2 tiles per CTA, both index chains up front ----
        const unsigned g = bid - (SCALAR_BLOCKS + COARSE_BLOCKS);  // < 1024
        const unsigned tile0 = g * 2;
        const unsigned tile1 = tile0 + 1;
        const unsigned d4t = t & (D4 - 1);   // d4 of every element this thread touches

        const unsigned b0 = tile0 >> 9, f0 = tile0 & (NF - 1);
        const unsigned b1 = tile1 >> 9, f1 = tile1 & (NF - 1);

        // Independent two-hop chains for both tiles (MLP=2 on the chase)
        const int fi0 = __ldg(&fidx[b0 * NF + f0]);
        const int fi1 = __ldg(&fidx[b1 * NF + f1]);
        const float4 c0 = __ldg(&coarse[(b0 * NB + (unsigned)fi0) * D4 + d4t]);
        const float4 c1 = __ldg(&coarse[(b1 * NB + (unsigned)fi1) * D4 + d4t]);
        const int bi0 = __ldg(&table[b0 * NB + fi0]);
        const int bi1 = __ldg(&table[b1 * NB + fi1]);

        const float4* __restrict__ bt0 = bank + (size_t)(b0 * NB + (unsigned)bi0) * TILE_F4;
        const float4* __restrict__ bt1 = bank + (size_t)(b1 * NB + (unsigned)bi1) * TILE_F4;
        float4* __restrict__ ot0 = o_fine_states + (size_t)tile0 * TILE_F4;
        float4* __restrict__ ot1 = o_fine_states + (size_t)tile1 * TILE_F4;

        float4 v[8];
        // Tile 0: 8 independent loads, streaming stores
        #pragma unroll
        for (int j = 0; j < 8; j++)
            v[j] = __ldg(&bt0[j * 256 + t]);
        #pragma unroll
        for (int j = 0; j < 8; j++)
            __stwt(&ot0[j * 256 + t],
                   make_float4(c0.x - v[j].x, c0.y - v[j].y,
                               c0.z - v[j].z, c0.w - v[j].w));

        // Tile 1: chain already resolved, loads issue immediately
        #pragma unroll
        for (int j = 0; j < 8; j++)
            v[j] = __ldg(&bt1[j * 256 + t]);
        #pragma unroll
        for (int j = 0; j < 8; j++)
            __stwt(&ot1[j * 256 + t],
                   make_float4(c1.x - v[j].x, c1.y - v[j].y,
                               c1.z - v[j].z, c1.w - v[j].w));
    }
}

extern "C" void kernel_launch(void* const* d_in, const int* in_sizes, int n_in,
                              void* d_out, int out_size)
{
    const float* fine_token_mask      = (const float*)d_in[0];
    const float* coarse_token_states  = (const float*)d_in[1];
    const float* coarse_token_mask    = (const float*)d_in[2];
    const int*   fine_block_indices   = (const int*)  d_in[3];
    const float* fine_block_scores    = (const float*)d_in[4];
    const int*   coarse_block_indices = (const int*)  d_in[5];
    const float* coarse_block_scores  = (const float*)d_in[6];
    const int*   cache_indice_table   = (const int*)  d_in[7];
    const float* cache_bank           = (const float*)d_in[8];

    float* out = (float*)d_out;

    const long long n_fine_states   = (long long)B * NF * BS * D;   // 16,777,216
    const long long n_fine_scalar   = (long long)B * NF * BS;       // 65,536
    const long long n_coarse_states = (long long)B * NC * D;        // 1,048,576
    const long long n_coarse_scalar = (long long)B * NC;            // 4,096

    float* o_fine_states   = out;
    float* o_fine_mask     = o_fine_states   + n_fine_states;
    float* o_fine_scores   = o_fine_mask     + n_fine_scalar;
    float* o_fine_dups     = o_fine_scores   + n_fine_scalar;
    float* o_coarse_states = o_fine_dups     + n_fine_scalar;
    float* o_coarse_mask   = o_coarse_states + n_coarse_states;
    float* o_coarse_scores = o_coarse_mask   + n_coarse_scalar;
    float* o_coarse_dups   = o_coarse_scores + n_coarse_scalar;

    fused_kernel<<<TOTAL_BLOCKS, 256>>>(
        (const float4*)coarse_token_states,
        (const float4*)cache_bank,
        fine_block_indices,
        cache_indice_table,
        fine_token_mask,
        fine_block_scores,
        coarse_token_mask,
        coarse_block_indices,
        coarse_block_scores,
        (float4*)o_fine_states,
        o_fine_mask, o_fine_scores, o_fine_dups,
        (float4*)o_coarse_states,
        o_coarse_mask, o_coarse_scores, o_coarse_dups);
}

// round 7
// speedup vs baseline: 1.4769x; 1.1815x over previous
#include <cuda_runtime.h>
#include <cstdint>

// Problem constants (fixed shapes)
#define B   4
#define NB  2048
#define BS  32
#define D   256
#define NF  512
#define NC  1024
#define D4  (D/4)              // 64 float4 per row
#define TILE_F4 (BS * D4)      // 2048 float4 per (b,f) tile

// Grid partition: scalar | coarse | fine (1 tile per fine CTA)
#define SCALAR_BLOCKS  64      // 65536 scalars, 4 per thread
#define COARSE_BLOCKS  256     // 2^18 float4, 4 per thread
#define FINE_CTAS      (B * NF)                       // 2048
#define TOTAL_BLOCKS   (SCALAR_BLOCKS + COARSE_BLOCKS + FINE_CTAS)

// L2 evict-last access policy (created once per thread, reused for all loads)
__device__ __forceinline__ uint64_t make_evict_last_policy() {
    uint64_t p;
    asm("createpolicy.fractional.L2::evict_last.b64 %0, 1.0;" : "=l"(p));
    return p;
}

// Bank-tile load with evict-last hint: pin the re-used read set in L2
__device__ __forceinline__ float4 ldg_evict_last(const float4* p, uint64_t pol) {
    float4 v;
    asm volatile("ld.global.nc.L2::cache_hint.v4.f32 {%0,%1,%2,%3}, [%4], %5;"
                 : "=f"(v.x), "=f"(v.y), "=f"(v.z), "=f"(v.w)
                 : "l"(p), "l"(pol));
    return v;
}

__global__ void __launch_bounds__(256) fused_kernel(
    const float4* __restrict__ coarse,    // [B,NB,D4]
    const float4* __restrict__ bank,      // [B,NB,BS,D4]
    const int*    __restrict__ fidx,      // [B,NF]
    const int*    __restrict__ table,     // [B,NB]
    const float*  __restrict__ ftm,       // [B, NB*BS]
    const float*  __restrict__ fscore,    // [B, NF]
    const float*  __restrict__ ctm,       // [B, NB]
    const int*    __restrict__ cidx,      // [B, NC]
    const float*  __restrict__ cscore,    // [B, NC]
    float4* __restrict__ o_fine_states,   // [B*NF] tiles of 2048 f4
    float*  __restrict__ o_fine_mask,
    float*  __restrict__ o_fine_scores,
    float*  __restrict__ o_fine_dups,
    float4* __restrict__ o_coarse_states, // [B,NC,D4]
    float*  __restrict__ o_coarse_mask,
    float*  __restrict__ o_coarse_scores,
    float*  __restrict__ o_coarse_dups)
{
    const unsigned bid = blockIdx.x;
    const unsigned t   = threadIdx.x;

    if (bid < SCALAR_BLOCKS) {
        // ---- all scalar outputs: 4 elements per thread ----
        #pragma unroll
        for (int j = 0; j < 4; j++) {
            const unsigned i = bid * 1024 + (unsigned)j * 256 + t;  // < 65536
            const unsigned s = i & (BS - 1);
            const unsigned f = (i >> 5) & (NF - 1);
            const unsigned b = i >> 14;

            const int fi = __ldg(&fidx[b * NF + f]);
            o_fine_mask[i]   = __ldg(&ftm[b * (NB * BS) + (unsigned)fi * BS + s]);
            o_fine_scores[i] = __ldg(&fscore[b * NF + f]);
            o_fine_dups[i]   = 1.0f;

            if (i < (unsigned)(B * NC)) {
                const unsigned c  = i & (NC - 1);
                const unsigned b2 = i >> 10;
                const int ci = __ldg(&cidx[b2 * NC + c]);
                o_coarse_mask[i]   = __ldg(&ctm[b2 * NB + (unsigned)ci]);
                o_coarse_scores[i] = __ldg(&cscore[i]);
                o_coarse_dups[i]   = 32.0f;
            }
        }
    }
    else if (bid < SCALAR_BLOCKS + COARSE_BLOCKS) {
        // ---- coarse token states gather: 4 float4 per thread (MLP=4) ----
        const unsigned base = (bid - SCALAR_BLOCKS) * 1024;
        float4 v[4];
        #pragma unroll
        for (int j = 0; j < 4; j++) {
            const unsigned i  = base + (unsigned)j * 256 + t;  // < 2^18
            const unsigned d4 = i & (D4 - 1);
            const unsigned c  = (i >> 6) & (NC - 1);
            const unsigned b  = i >> 16;
            const int ci = __ldg(&cidx[b * NC + c]);
            v[j] = __ldg(&coarse[(b * NB + (unsigned)ci) * D4 + d4]);
        }
        #pragma unroll
        for (int j = 0; j < 4; j++)
            __stcs(&o_coarse_states[base + (unsigned)j * 256 + t], v[j]);
    }
    else {
        // ---- fine token states: one tile per CTA ----
        const unsigned tile = bid - (SCALAR_BLOCKS + COARSE_BLOCKS);  // < 2048
        const unsigned b = tile >> 9;        // / NF
        const unsigned f = tile & (NF - 1);

        const int fi = __ldg(&fidx[b * NF + f]);
        // d4 of every element this thread touches is (t & 63): 256 % 64 == 0
        const float4 c = __ldg(&coarse[(b * NB + (unsigned)fi) * D4 + (t & (D4 - 1))]);
        const int bi = __ldg(&table[b * NB + fi]);

        const float4* __restrict__ bt = bank + (size_t)(b * NB + (unsigned)bi) * TILE_F4;
        float4*       __restrict__ ot = o_fine_states + (size_t)tile * TILE_F4;

        const uint64_t pol = make_evict_last_policy();

        // 8 independent evict-last loads (MLP=8), evict-first streaming stores
        float4 v[8];
        #pragma unroll
        for (int j = 0; j < 8; j++)
            v[j] = ldg_evict_last(&bt[j * 256 + t], pol);

        #pragma unroll
        for (int j = 0; j < 8; j++)
            __stcs(&ot[j * 256 + t],
                   make_float4(c.x - v[j].x, c.y - v[j].y,
                               c.z - v[j].z, c.w - v[j].w));
    }
}

extern "C" void kernel_launch(void* const* d_in, const int* in_sizes, int n_in,
                              void* d_out, int out_size)
{
    const float* fine_token_mask      = (const float*)d_in[0];
    const float* coarse_token_states  = (const float*)d_in[1];
    const float* coarse_token_mask    = (const float*)d_in[2];
    const int*   fine_block_indices   = (const int*)  d_in[3];
    const float* fine_block_scores    = (const float*)d_in[4];
    const int*   coarse_block_indices = (const int*)  d_in[5];
    const float* coarse_block_scores  = (const float*)d_in[6];
    const int*   cache_indice_table   = (const int*)  d_in[7];
    const float* cache_bank           = (const float*)d_in[8];

    float* out = (float*)d_out;

    const long long n_fine_states   = (long long)B * NF * BS * D;   // 16,777,216
    const long long n_fine_scalar   = (long long)B * NF * BS;       // 65,536
    const long long n_coarse_states = (long long)B * NC * D;        // 1,048,576
    const long long n_coarse_scalar = (long long)B * NC;            // 4,096

    float* o_fine_states   = out;
    float* o_fine_mask     = o_fine_states   + n_fine_states;
    float* o_fine_scores   = o_fine_mask     + n_fine_scalar;
    float* o_fine_dups     = o_fine_scores   + n_fine_scalar;
    float* o_coarse_states = o_fine_dups     + n_fine_scalar;
    float* o_coarse_mask   = o_coarse_states + n_coarse_states;
    float* o_coarse_scores = o_coarse_mask   + n_coarse_scalar;
    float* o_coarse_dups   = o_coarse_scores + n_coarse_scalar;

    fused_kernel<<<TOTAL_BLOCKS, 256>>>(
        (const float4*)coarse_token_states,
        (const float4*)cache_bank,
        fine_block_indices,
        cache_indice_table,
        fine_token_mask,
        fine_block_scores,
        coarse_token_mask,
        coarse_block_indices,
        coarse_block_scores,
        (float4*)o_fine_states,
        o_fine_mask, o_fine_scores, o_fine_dups,
        (float4*)o_coarse_states,
        o_coarse_mask, o_coarse_scores, o_coarse_dups);
}

// round 8
// speedup vs baseline: 1.4907x; 1.0093x over previous
#include <cuda_runtime.h>
#include <cstdint>

// Problem constants (fixed shapes)
#define B   4
#define NB  2048
#define BS  32
#define D   256
#define NF  512
#define NC  1024
#define D8  (D/8)              // 32 float8 per row
#define TILE_F8 (BS * D8)      // 1024 float8 per (b,f) tile (32 KB)

// Grid partition: scalar | coarse | fine (1 tile per fine CTA)
#define SCALAR_BLOCKS  64      // 65536 scalars, 4 per thread
#define COARSE_BLOCKS  256     // 2^17 float8, 2 per thread
#define FINE_CTAS      (B * NF)                       // 2048
#define TOTAL_BLOCKS   (SCALAR_BLOCKS + COARSE_BLOCKS + FINE_CTAS)

// 256-bit load, L2 evict-last (pin re-used bank set in L2)
__device__ __forceinline__ void ldg256_el(const float* p, float v[8]) {
    unsigned r0,r1,r2,r3,r4,r5,r6,r7;
    asm volatile("ld.global.nc.L2::evict_last.v8.b32 {%0,%1,%2,%3,%4,%5,%6,%7}, [%8];"
                 : "=r"(r0),"=r"(r1),"=r"(r2),"=r"(r3),
                   "=r"(r4),"=r"(r5),"=r"(r6),"=r"(r7)
                 : "l"(p));
    v[0]=__uint_as_float(r0); v[1]=__uint_as_float(r1);
    v[2]=__uint_as_float(r2); v[3]=__uint_as_float(r3);
    v[4]=__uint_as_float(r4); v[5]=__uint_as_float(r5);
    v[6]=__uint_as_float(r6); v[7]=__uint_as_float(r7);
}

// 256-bit plain load (for coarse row)
__device__ __forceinline__ void ldg256(const float* p, float v[8]) {
    unsigned r0,r1,r2,r3,r4,r5,r6,r7;
    asm volatile("ld.global.nc.v8.b32 {%0,%1,%2,%3,%4,%5,%6,%7}, [%8];"
                 : "=r"(r0),"=r"(r1),"=r"(r2),"=r"(r3),
                   "=r"(r4),"=r"(r5),"=r"(r6),"=r"(r7)
                 : "l"(p));
    v[0]=__uint_as_float(r0); v[1]=__uint_as_float(r1);
    v[2]=__uint_as_float(r2); v[3]=__uint_as_float(r3);
    v[4]=__uint_as_float(r4); v[5]=__uint_as_float(r5);
    v[6]=__uint_as_float(r6); v[7]=__uint_as_float(r7);
}

// 256-bit store with evict-first policy (don't pollute L2 with dead writes)
__device__ __forceinline__ void stg256_ef(float* p, const float v[8], uint64_t pol) {
    asm volatile("st.global.L2::cache_hint.v8.b32 [%0], {%1,%2,%3,%4,%5,%6,%7,%8}, %9;"
                 :: "l"(p),
                    "r"(__float_as_uint(v[0])), "r"(__float_as_uint(v[1])),
                    "r"(__float_as_uint(v[2])), "r"(__float_as_uint(v[3])),
                    "r"(__float_as_uint(v[4])), "r"(__float_as_uint(v[5])),
                    "r"(__float_as_uint(v[6])), "r"(__float_as_uint(v[7])),
                    "l"(pol)
                 : "memory");
}

__device__ __forceinline__ uint64_t make_evict_first_policy() {
    uint64_t p;
    asm("createpolicy.fractional.L2::evict_first.b64 %0, 1.0;" : "=l"(p));
    return p;
}

__global__ void __launch_bounds__(256) fused_kernel(
    const float*  __restrict__ coarse,    // [B,NB,D]
    const float*  __restrict__ bank,      // [B,NB,BS,D]
    const int*    __restrict__ fidx,      // [B,NF]
    const int*    __restrict__ table,     // [B,NB]
    const float*  __restrict__ ftm,       // [B, NB*BS]
    const float*  __restrict__ fscore,    // [B, NF]
    const float*  __restrict__ ctm,       // [B, NB]
    const int*    __restrict__ cidx,      // [B, NC]
    const float*  __restrict__ cscore,    // [B, NC]
    float*  __restrict__ o_fine_states,   // [B*NF] tiles of 1024 f8
    float*  __restrict__ o_fine_mask,
    float*  __restrict__ o_fine_scores,
    float*  __restrict__ o_fine_dups,
    float*  __restrict__ o_coarse_states, // [B,NC,D]
    float*  __restrict__ o_coarse_mask,
    float*  __restrict__ o_coarse_scores,
    float*  __restrict__ o_coarse_dups)
{
    const unsigned bid = blockIdx.x;
    const unsigned t   = threadIdx.x;

    if (bid < SCALAR_BLOCKS) {
        // ---- all scalar outputs: 4 elements per thread ----
        #pragma unroll
        for (int j = 0; j < 4; j++) {
            const unsigned i = bid * 1024 + (unsigned)j * 256 + t;  // < 65536
            const unsigned s = i & (BS - 1);
            const unsigned f = (i >> 5) & (NF - 1);
            const unsigned b = i >> 14;

            const int fi = __ldg(&fidx[b * NF + f]);
            o_fine_mask[i]   = __ldg(&ftm[b * (NB * BS) + (unsigned)fi * BS + s]);
            o_fine_scores[i] = __ldg(&fscore[b * NF + f]);
            o_fine_dups[i]   = 1.0f;

            if (i < (unsigned)(B * NC)) {
                const unsigned c  = i & (NC - 1);
                const unsigned b2 = i >> 10;
                const int ci = __ldg(&cidx[b2 * NC + c]);
                o_coarse_mask[i]   = __ldg(&ctm[b2 * NB + (unsigned)ci]);
                o_coarse_scores[i] = __ldg(&cscore[i]);
                o_coarse_dups[i]   = 32.0f;
            }
        }
    }
    else if (bid < SCALAR_BLOCKS + COARSE_BLOCKS) {
        // ---- coarse token states gather: 2 float8 per thread ----
        const uint64_t pol = make_evict_first_policy();
        const unsigned base = (bid - SCALAR_BLOCKS) * 512;   // in float8 units
        float v[2][8];
        unsigned idx[2];
        #pragma unroll
        for (int j = 0; j < 2; j++) {
            const unsigned i  = base + (unsigned)j * 256 + t;  // < 2^17
            idx[j] = i;
            const unsigned d8 = i & (D8 - 1);
            const unsigned c  = (i >> 5) & (NC - 1);
            const unsigned b  = i >> 15;
            const int ci = __ldg(&cidx[b * NC + c]);
            ldg256(&coarse[((size_t)(b * NB + (unsigned)ci) * D8 + d8) * 8], v[j]);
        }
        #pragma unroll
        for (int j = 0; j < 2; j++)
            stg256_ef(&o_coarse_states[(size_t)idx[j] * 8], v[j], pol);
    }
    else {
        // ---- fine token states: one tile per CTA, 4 float8 per thread ----
        const unsigned tile = bid - (SCALAR_BLOCKS + COARSE_BLOCKS);  // < 2048
        const unsigned b = tile >> 9;        // / NF
        const unsigned f = tile & (NF - 1);

        const int fi = __ldg(&fidx[b * NF + f]);
        // d8 of every element this thread touches is (t & 31): 256 % 32 == 0
        float c[8];
        ldg256(&coarse[((size_t)(b * NB + (unsigned)fi) * D8 + (t & (D8 - 1))) * 8], c);
        const int bi = __ldg(&table[b * NB + fi]);

        const float* __restrict__ bt = bank + (size_t)(b * NB + (unsigned)bi) * TILE_F8 * 8;
        float*       __restrict__ ot = o_fine_states + (size_t)tile * TILE_F8 * 8;

        const uint64_t pol = make_evict_first_policy();

        // 4 independent 256-bit evict-last loads (1 KB in flight per thread)
        float v[4][8];
        #pragma unroll
        for (int j = 0; j < 4; j++)
            ldg256_el(&bt[(size_t)(j * 256 + t) * 8], v[j]);

        #pragma unroll
        for (int j = 0; j < 4; j++) {
            float r[8];
            #pragma unroll
            for (int e = 0; e < 8; e++)
                r[e] = c[e] - v[j][e];
            stg256_ef(&ot[(size_t)(j * 256 + t) * 8], r, pol);
        }
    }
}

extern "C" void kernel_launch(void* const* d_in, const int* in_sizes, int n_in,
                              void* d_out, int out_size)
{
    const float* fine_token_mask      = (const float*)d_in[0];
    const float* coarse_token_states  = (const float*)d_in[1];
    const float* coarse_token_mask    = (const float*)d_in[2];
    const int*   fine_block_indices   = (const int*)  d_in[3];
    const float* fine_block_scores    = (const float*)d_in[4];
    const int*   coarse_block_indices = (const int*)  d_in[5];
    const float* coarse_block_scores  = (const float*)d_in[6];
    const int*   cache_indice_table   = (const int*)  d_in[7];
    const float* cache_bank           = (const float*)d_in[8];

    float* out = (float*)d_out;

    const long long n_fine_states   = (long long)B * NF * BS * D;   // 16,777,216
    const long long n_fine_scalar   = (long long)B * NF * BS;       // 65,536
    const long long n_coarse_states = (long long)B * NC * D;        // 1,048,576
    const long long n_coarse_scalar = (long long)B * NC;            // 4,096

    float* o_fine_states   = out;
    float* o_fine_mask     = o_fine_states   + n_fine_states;
    float* o_fine_scores   = o_fine_mask     + n_fine_scalar;
    float* o_fine_dups     = o_fine_scores   + n_fine_scalar;
    float* o_coarse_states = o_fine_dups     + n_fine_scalar;
    float* o_coarse_mask   = o_coarse_states + n_coarse_states;
    float* o_coarse_scores = o_coarse_mask   + n_coarse_scalar;
    float* o_coarse_dups   = o_coarse_scores + n_coarse_scalar;

    fused_kernel<<<TOTAL_BLOCKS, 256>>>(
        coarse_token_states,
        cache_bank,
        fine_block_indices,
        cache_indice_table,
        fine_token_mask,
        fine_block_scores,
        coarse_token_mask,
        coarse_block_indices,
        coarse_block_scores,
        o_fine_states,
        o_fine_mask, o_fine_scores, o_fine_dups,
        o_coarse_states,
        o_coarse_mask, o_coarse_scores, o_coarse_dups);
}